// round 4
// baseline (speedup 1.0000x reference)
#include <cuda_runtime.h>
#include <math.h>

#define T_LEN 4096
#define NTHREADS 256
#define CHUNK 16   // T_LEN / NTHREADS

__global__ __launch_bounds__(NTHREADS, 8)
void garch_kernel(const float* __restrict__ x,
                  const float* __restrict__ omega_log,
                  const float* __restrict__ alpha_log,
                  const float* __restrict__ beta_log,
                  float* __restrict__ out)
{
    __shared__ float sx[T_LEN];       // row buffer, reused for outputs
    __shared__ float As[NTHREADS];
    __shared__ float Bs[NTHREADS];
    __shared__ float red_sum[NTHREADS / 32];
    __shared__ float red_sq[NTHREADS / 32];
    __shared__ float s0_sh;

    const int b   = blockIdx.x;
    const int tid = threadIdx.x;

    // ---- scalar params (L2-cached reads; all blocks read same 3 floats) ----
    const float ea    = expf(alpha_log[0]);
    const float eb    = expf(beta_log[0]);
    const float denom = 1.0f + ea + eb;
    const float omega = expf(omega_log[0]);
    const float alpha = ea / denom;
    const float beta  = eb / denom;

    // ---- phase 0: coalesced load row into smem + fused sum / sumsq ----
    const float* xrow = x + (size_t)b * T_LEN;
    float sum = 0.0f, sq = 0.0f;
    #pragma unroll
    for (int i = tid; i < T_LEN; i += NTHREADS) {
        float v = xrow[i];
        sx[i] = v;
        sum += v;
        sq  = fmaf(v, v, sq);
    }
    // warp reduce
    #pragma unroll
    for (int off = 16; off > 0; off >>= 1) {
        sum += __shfl_down_sync(0xFFFFFFFFu, sum, off);
        sq  += __shfl_down_sync(0xFFFFFFFFu, sq,  off);
    }
    if ((tid & 31) == 0) {
        red_sum[tid >> 5] = sum;
        red_sq [tid >> 5] = sq;
    }
    __syncthreads();
    if (tid == 0) {
        float ts = 0.0f, tq = 0.0f;
        #pragma unroll
        for (int w = 0; w < NTHREADS / 32; w++) { ts += red_sum[w]; tq += red_sq[w]; }
        // unbiased variance: (sumsq - sum^2/n) / (n-1)
        float s0 = (tq - ts * ts * (1.0f / (float)T_LEN)) * (1.0f / (float)(T_LEN - 1));
        s0_sh = s0;
    }
    __syncthreads();
    const float s0 = s0_sh;

    // ---- phase 1: per-thread chunk -> registers, local affine (A, B) ----
    // thread k owns steps t in [16k+1, 16k+16] (clamped to t <= 4095);
    // step t consumes x[t-1]^2, i.e. smem indices [16k .. 16k+15].
    float x2r[CHUNK];
    const int base = tid * CHUNK;
    #pragma unroll
    for (int j = 0; j < CHUNK; j++) {
        float v = sx[base + j];
        x2r[j] = v * v;
    }

    float A = 1.0f, Bv = 0.0f;
    #pragma unroll
    for (int j = 0; j < CHUNK; j++) {
        int t = base + 1 + j;
        if (t < T_LEN) {
            float c = fmaf(alpha, x2r[j], omega);
            Bv = fmaf(beta, Bv, c);
            A *= beta;
        }
    }

    // ---- phase 2: Hillis-Steele inclusive scan over affine transforms ----
    As[tid] = A;
    Bs[tid] = Bv;
    __syncthreads();
    #pragma unroll
    for (int off = 1; off < NTHREADS; off <<= 1) {
        float a2 = As[tid], b2 = Bs[tid];
        float a1 = 0.0f, b1 = 0.0f;
        bool has = (tid >= off);
        if (has) { a1 = As[tid - off]; b1 = Bs[tid - off]; }
        __syncthreads();
        if (has) {
            As[tid] = a1 * a2;             // later ∘ earlier
            Bs[tid] = fmaf(a2, b1, b2);
        }
        __syncthreads();
    }

    // incoming state for this chunk = composite of chunks [0..tid-1] applied to s0
    float s = (tid == 0) ? s0 : fmaf(As[tid - 1], s0, Bs[tid - 1]);

    // ---- phase 3: replay chunk, write sqrt into smem (registers hold x2) ----
    if (tid == 0) sx[0] = sqrtf(s0);
    #pragma unroll
    for (int j = 0; j < CHUNK; j++) {
        int t = base + 1 + j;
        if (t < T_LEN) {
            float c = fmaf(alpha, x2r[j], omega);
            s = fmaf(beta, s, c);
            sx[t] = sqrtf(s);
        }
    }
    __syncthreads();

    // ---- phase 4: coalesced store ----
    float* orow = out + (size_t)b * T_LEN;
    #pragma unroll
    for (int i = tid; i < T_LEN; i += NTHREADS) {
        orow[i] = sx[i];
    }
}

extern "C" void kernel_launch(void* const* d_in, const int* in_sizes, int n_in,
                              void* d_out, int out_size)
{
    const float* x         = (const float*)d_in[0];
    const float* omega_log = (const float*)d_in[1];
    const float* alpha_log = (const float*)d_in[2];
    const float* beta_log  = (const float*)d_in[3];
    float* out = (float*)d_out;

    const int B = in_sizes[0] / T_LEN;   // 4096
    garch_kernel<<<B, NTHREADS>>>(x, omega_log, alpha_log, beta_log, out);
}

// round 5
// speedup vs baseline: 1.7463x; 1.7463x over previous
#include <cuda_runtime.h>
#include <math.h>

#define T_LEN    4096
#define NTHREADS 1024
#define CHUNK    4            // T_LEN / NTHREADS
#define NWARPS   (NTHREADS / 32)

__global__ __launch_bounds__(NTHREADS, 2)
void garch_kernel(const float4* __restrict__ x4,
                  const float* __restrict__ omega_log,
                  const float* __restrict__ alpha_log,
                  const float* __restrict__ beta_log,
                  float4* __restrict__ out4)
{
    __shared__ float Aw[NWARPS];     // warp affine aggregates
    __shared__ float Bw[NWARPS];
    __shared__ float sumw[NWARPS];   // warp partial sums for variance
    __shared__ float sqw[NWARPS];
    __shared__ float s0_sh;

    const int tid  = threadIdx.x;
    const int lane = tid & 31;
    const int wid  = tid >> 5;

    // ---- scalar params (tiny, L2-resident) ----
    const float ea    = expf(alpha_log[0]);
    const float eb    = expf(beta_log[0]);
    const float denom = 1.0f + ea + eb;
    const float omega = expf(omega_log[0]);
    const float alpha = ea / denom;
    const float beta  = eb / denom;

    // ---- load: one coalesced float4 per thread ----
    const size_t row4 = (size_t)blockIdx.x * NTHREADS;
    float4 v = x4[row4 + tid];

    float x2[CHUNK];
    x2[0] = v.x * v.x; x2[1] = v.y * v.y;
    x2[2] = v.z * v.z; x2[3] = v.w * v.w;

    // ---- variance partials ----
    float sum = v.x + v.y + v.z + v.w;
    float sq  = x2[0] + x2[1] + x2[2] + x2[3];
    #pragma unroll
    for (int off = 16; off > 0; off >>= 1) {
        sum += __shfl_xor_sync(0xFFFFFFFFu, sum, off);
        sq  += __shfl_xor_sync(0xFFFFFFFFu, sq,  off);
    }

    // ---- local affine over 4 steps:  s -> A*s + B ----
    float A = 1.0f, B = 0.0f;
    #pragma unroll
    for (int j = 0; j < CHUNK; j++) {
        float c = fmaf(alpha, x2[j], omega);
        B = fmaf(beta, B, c);
        A *= beta;
    }

    // ---- warp-level inclusive scan of affine pairs (registers only) ----
    // compose earlier (a1,b1) then own-later (A,B): A'=a1*A, B'=A*b1+B
    #pragma unroll
    for (int off = 1; off < 32; off <<= 1) {
        float a_up = __shfl_up_sync(0xFFFFFFFFu, A, off);
        float b_up = __shfl_up_sync(0xFFFFFFFFu, B, off);
        if (lane >= off) {
            B = fmaf(A, b_up, B);
            A = A * a_up;
        }
    }

    // ---- publish warp aggregates + variance partials ----
    if (lane == 31) { Aw[wid] = A; Bw[wid] = B; }
    if (lane == 0)  { sumw[wid] = sum; sqw[wid] = sq; }
    __syncthreads();

    // ---- warp 0: scan the 32 warp aggregates AND finish the variance ----
    if (wid == 0) {
        float a = Aw[lane], b = Bw[lane];
        #pragma unroll
        for (int off = 1; off < NWARPS; off <<= 1) {
            float a_up = __shfl_up_sync(0xFFFFFFFFu, a, off);
            float b_up = __shfl_up_sync(0xFFFFFFFFu, b, off);
            if (lane >= off) {
                b = fmaf(a, b_up, b);
                a = a * a_up;
            }
        }
        Aw[lane] = a;   // inclusive across warps [0..lane]
        Bw[lane] = b;

        float ts = sumw[lane], tq = sqw[lane];
        #pragma unroll
        for (int off = 16; off > 0; off >>= 1) {
            ts += __shfl_xor_sync(0xFFFFFFFFu, ts, off);
            tq += __shfl_xor_sync(0xFFFFFFFFu, tq, off);
        }
        if (lane == 0) {
            s0_sh = (tq - ts * ts * (1.0f / (float)T_LEN))
                    * (1.0f / (float)(T_LEN - 1));
        }
    }
    __syncthreads();
    const float s0 = s0_sh;

    // ---- total exclusive prefix for this thread ----
    // thread-exclusive within warp: shift inclusive down by one lane
    float a_exc = __shfl_up_sync(0xFFFFFFFFu, A, 1);
    float b_exc = __shfl_up_sync(0xFFFFFFFFu, B, 1);
    if (lane == 0) { a_exc = 1.0f; b_exc = 0.0f; }
    // warp prefix (earlier) composed with thread-exclusive (later)
    float a_wp = 1.0f, b_wp = 0.0f;
    if (wid > 0) { a_wp = Aw[wid - 1]; b_wp = Bw[wid - 1]; }
    float a_tot = a_wp * a_exc;
    float b_tot = fmaf(a_exc, b_wp, b_exc);

    // incoming state s_{4*tid}
    float s = fmaf(a_tot, s0, b_tot);

    // ---- replay 3 steps; outputs are {sqrt(s_in), sqrt(s1), sqrt(s2), sqrt(s3)} ----
    float4 o;
    o.x = sqrtf(s);
    float c0 = fmaf(alpha, x2[0], omega);
    s = fmaf(beta, s, c0);
    o.y = sqrtf(s);
    float c1 = fmaf(alpha, x2[1], omega);
    s = fmaf(beta, s, c1);
    o.z = sqrtf(s);
    float c2 = fmaf(alpha, x2[2], omega);
    s = fmaf(beta, s, c2);
    o.w = sqrtf(s);

    out4[row4 + tid] = o;
}

extern "C" void kernel_launch(void* const* d_in, const int* in_sizes, int n_in,
                              void* d_out, int out_size)
{
    const float4* x4       = (const float4*)d_in[0];
    const float* omega_log = (const float*)d_in[1];
    const float* alpha_log = (const float*)d_in[2];
    const float* beta_log  = (const float*)d_in[3];
    float4* out4 = (float4*)d_out;

    const int B = in_sizes[0] / T_LEN;   // 4096 rows
    garch_kernel<<<B, NTHREADS>>>(x4, omega_log, alpha_log, beta_log, out4);
}

// round 6
// speedup vs baseline: 2.6086x; 1.4937x over previous
#include <cuda_runtime.h>
#include <math.h>

#define T_LEN    4096
#define NTHREADS 256
#define NW4      1024            // float4s per row
#define NWARPS   (NTHREADS / 32)
#define FULL     0xFFFFFFFFu

// XOR swizzle on float4 index: permutes low 2 bits by bits [3:4].
// Conflict-free for both access patterns (verified per 8-lane LDS.128 phase):
//   coalesced  i = 256*j + tid   and   chunked  i = 4*tid + j
__device__ __forceinline__ int sw(int i) {
    return (i & ~3) | ((i ^ (i >> 3)) & 3);
}

__global__ __launch_bounds__(NTHREADS, 8)
void garch_kernel(const float4* __restrict__ x4,
                  const float* __restrict__ omega_log,
                  const float* __restrict__ alpha_log,
                  const float* __restrict__ beta_log,
                  float4* __restrict__ out4)
{
    __shared__ float4 sm4[NW4];          // row staging (in, then out)
    __shared__ float Aw[NWARPS], Bw[NWARPS];
    __shared__ float sumw[NWARPS], sqw[NWARPS];
    __shared__ float s0_sh;

    const int tid  = threadIdx.x;
    const int lane = tid & 31;
    const int wid  = tid >> 5;

    // ---- scalar params ----
    const float ea    = expf(alpha_log[0]);
    const float eb    = expf(beta_log[0]);
    const float denom = 1.0f + ea + eb;
    const float omega = expf(omega_log[0]);
    const float alpha = ea / denom;
    const float beta  = eb / denom;

    // ---- stage in: coalesced LDG.128 -> swizzled smem; fused variance partials ----
    const size_t row4 = (size_t)blockIdx.x * NW4;
    float sum = 0.0f, sq = 0.0f;
    #pragma unroll
    for (int j = 0; j < 4; j++) {
        float4 v = x4[row4 + j * NTHREADS + tid];
        sum += v.x + v.y + v.z + v.w;
        sq = fmaf(v.x, v.x, sq); sq = fmaf(v.y, v.y, sq);
        sq = fmaf(v.z, v.z, sq); sq = fmaf(v.w, v.w, sq);
        sm4[sw(j * NTHREADS + tid)] = v;
    }
    #pragma unroll
    for (int off = 16; off > 0; off >>= 1) {
        sum += __shfl_xor_sync(FULL, sum, off);
        sq  += __shfl_xor_sync(FULL, sq,  off);
    }
    if (lane == 0) { sumw[wid] = sum; sqw[wid] = sq; }
    __syncthreads();

    // ---- local affine over this thread's 16 steps: s -> A*s + B ----
    float B = 0.0f;
    #pragma unroll
    for (int j = 0; j < 4; j++) {
        float4 c = sm4[sw(4 * tid + j)];
        B = fmaf(beta, B, fmaf(alpha, c.x * c.x, omega));
        B = fmaf(beta, B, fmaf(alpha, c.y * c.y, omega));
        B = fmaf(beta, B, fmaf(alpha, c.z * c.z, omega));
        B = fmaf(beta, B, fmaf(alpha, c.w * c.w, omega));
    }
    const float b2 = beta * beta, b4 = b2 * b2, b8 = b4 * b4;
    float A = b8 * b8;              // beta^16, thread-invariant

    // ---- warp inclusive scan of affine pairs ----
    #pragma unroll
    for (int off = 1; off < 32; off <<= 1) {
        float a_up = __shfl_up_sync(FULL, A, off);
        float b_up = __shfl_up_sync(FULL, B, off);
        if (lane >= off) {
            B = fmaf(A, b_up, B);
            A *= a_up;
        }
    }
    if (lane == 31) { Aw[wid] = A; Bw[wid] = B; }
    __syncthreads();

    // ---- warp 0: scan the 8 warp aggregates + finish variance ----
    if (wid == 0) {
        float a = (lane < NWARPS) ? Aw[lane] : 1.0f;
        float b = (lane < NWARPS) ? Bw[lane] : 0.0f;
        #pragma unroll
        for (int off = 1; off < NWARPS; off <<= 1) {
            float a_up = __shfl_up_sync(FULL, a, off);
            float b_up = __shfl_up_sync(FULL, b, off);
            if (lane >= off) {
                b = fmaf(a, b_up, b);
                a *= a_up;
            }
        }
        if (lane < NWARPS) { Aw[lane] = a; Bw[lane] = b; }

        float ts = (lane < NWARPS) ? sumw[lane] : 0.0f;
        float tq = (lane < NWARPS) ? sqw[lane]  : 0.0f;
        #pragma unroll
        for (int off = 4; off > 0; off >>= 1) {       // lanes 0..7 closed under xor
            ts += __shfl_xor_sync(FULL, ts, off);
            tq += __shfl_xor_sync(FULL, tq, off);
        }
        if (lane == 0) {
            s0_sh = (tq - ts * ts * (1.0f / (float)T_LEN))
                    * (1.0f / (float)(T_LEN - 1));
        }
    }
    __syncthreads();
    const float s0 = s0_sh;

    // ---- exclusive prefix for this thread ----
    float a_exc = __shfl_up_sync(FULL, A, 1);
    float b_exc = __shfl_up_sync(FULL, B, 1);
    if (lane == 0) { a_exc = 1.0f; b_exc = 0.0f; }
    float a_wp = 1.0f, b_wp = 0.0f;
    if (wid > 0) { a_wp = Aw[wid - 1]; b_wp = Bw[wid - 1]; }
    float s = fmaf(a_wp * a_exc, s0, fmaf(a_exc, b_wp, b_exc));   // s_{16*tid}

    // ---- replay: read chunk from smem, write sqrt states back in place ----
    #pragma unroll
    for (int j = 0; j < 4; j++) {
        const int idx = sw(4 * tid + j);
        float4 c = sm4[idx];
        float4 o;
        o.x = s * rsqrtf(s);
        s = fmaf(beta, s, fmaf(alpha, c.x * c.x, omega));
        o.y = s * rsqrtf(s);
        s = fmaf(beta, s, fmaf(alpha, c.y * c.y, omega));
        o.z = s * rsqrtf(s);
        s = fmaf(beta, s, fmaf(alpha, c.z * c.z, omega));
        o.w = s * rsqrtf(s);
        s = fmaf(beta, s, fmaf(alpha, c.w * c.w, omega));  // feeds next j (last one discarded)
        sm4[idx] = o;
    }
    __syncthreads();

    // ---- stage out: swizzled smem -> coalesced STG.128 ----
    #pragma unroll
    for (int j = 0; j < 4; j++) {
        out4[row4 + j * NTHREADS + tid] = sm4[sw(j * NTHREADS + tid)];
    }
}

extern "C" void kernel_launch(void* const* d_in, const int* in_sizes, int n_in,
                              void* d_out, int out_size)
{
    const float4* x4       = (const float4*)d_in[0];
    const float* omega_log = (const float*)d_in[1];
    const float* alpha_log = (const float*)d_in[2];
    const float* beta_log  = (const float*)d_in[3];
    float4* out4 = (float4*)d_out;

    const int B = in_sizes[0] / T_LEN;   // 4096 rows
    garch_kernel<<<B, NTHREADS>>>(x4, omega_log, alpha_log, beta_log, out4);
}

// round 7
// speedup vs baseline: 2.9194x; 1.1192x over previous
#include <cuda_runtime.h>
#include <math.h>

#define T_LEN    4096
#define NTHREADS 256
#define NSEG     4               // segments of 1024 elements (256 float4s)
#define NWARPS   (NTHREADS / 32)
#define FULL     0xFFFFFFFFu

__global__ __launch_bounds__(NTHREADS, 4)
void garch_kernel(const float4* __restrict__ x4,
                  const float* __restrict__ omega_log,
                  const float* __restrict__ alpha_log,
                  const float* __restrict__ beta_log,
                  float4* __restrict__ out4)
{
    // tiny smem: per-segment per-warp affine aggregates + variance partials
    __shared__ float AwS[NSEG][NWARPS];
    __shared__ float BwS[NSEG][NWARPS];
    __shared__ float sumw[NWARPS], sqw[NWARPS];
    __shared__ float s0_sh;

    const int tid  = threadIdx.x;
    const int lane = tid & 31;
    const int wid  = tid >> 5;

    // ---- scalar params ----
    const float ea    = expf(alpha_log[0]);
    const float eb    = expf(beta_log[0]);
    const float denom = 1.0f + ea + eb;
    const float omega = expf(omega_log[0]);
    const float alpha = ea / denom;
    const float beta  = eb / denom;
    const float b2 = beta * beta;
    const float beta4 = b2 * b2;          // per-thread A is invariant

    // ---- load: 4 coalesced float4 per thread; the float4 IS the chunk ----
    const size_t row4 = (size_t)blockIdx.x * (NSEG * NTHREADS);
    float4 v[NSEG];
    #pragma unroll
    for (int j = 0; j < NSEG; j++)
        v[j] = x4[row4 + j * NTHREADS + tid];

    // ---- variance partials over all 16 values ----
    float sum = 0.0f, sq = 0.0f;
    #pragma unroll
    for (int j = 0; j < NSEG; j++) {
        sum += v[j].x + v[j].y + v[j].z + v[j].w;
        sq = fmaf(v[j].x, v[j].x, sq); sq = fmaf(v[j].y, v[j].y, sq);
        sq = fmaf(v[j].z, v[j].z, sq); sq = fmaf(v[j].w, v[j].w, sq);
    }
    #pragma unroll
    for (int off = 16; off > 0; off >>= 1) {
        sum += __shfl_xor_sync(FULL, sum, off);
        sq  += __shfl_xor_sync(FULL, sq,  off);
    }
    if (lane == 0) { sumw[wid] = sum; sqw[wid] = sq; }

    // ---- per-segment local affine over the thread's 4 steps ----
    float A[NSEG], B[NSEG];
    #pragma unroll
    for (int j = 0; j < NSEG; j++) {
        float b = fmaf(alpha, v[j].x * v[j].x, omega);
        b = fmaf(beta, b, fmaf(alpha, v[j].y * v[j].y, omega));
        b = fmaf(beta, b, fmaf(alpha, v[j].z * v[j].z, omega));
        b = fmaf(beta, b, fmaf(alpha, v[j].w * v[j].w, omega));
        B[j] = b;
        A[j] = beta4;
    }

    // ---- 4 independent warp inclusive scans (interleaved for ILP) ----
    #pragma unroll
    for (int off = 1; off < 32; off <<= 1) {
        float au[NSEG], bu[NSEG];
        #pragma unroll
        for (int j = 0; j < NSEG; j++) {
            au[j] = __shfl_up_sync(FULL, A[j], off);
            bu[j] = __shfl_up_sync(FULL, B[j], off);
        }
        if (lane >= off) {
            #pragma unroll
            for (int j = 0; j < NSEG; j++) {
                B[j] = fmaf(A[j], bu[j], B[j]);
                A[j] *= au[j];
            }
        }
    }
    if (lane == 31) {
        #pragma unroll
        for (int j = 0; j < NSEG; j++) { AwS[j][wid] = A[j]; BwS[j][wid] = B[j]; }
    }
    __syncthreads();

    // ---- warp 0: four 8-element cross-warp scans in parallel (8-lane groups) ----
    if (wid == 0) {
        const int g  = lane >> 3;    // segment
        const int l8 = lane & 7;     // warp index within segment
        float a = AwS[g][l8], b = BwS[g][l8];
        #pragma unroll
        for (int off = 1; off < NWARPS; off <<= 1) {
            float au = __shfl_up_sync(FULL, a, off);
            float bu = __shfl_up_sync(FULL, b, off);
            if (l8 >= off) { b = fmaf(a, bu, b); a *= au; }
        }
        AwS[g][l8] = a;              // inclusive over warps [0..l8] of segment g
        BwS[g][l8] = b;
    }
    // ---- warp 1: finish variance concurrently ----
    if (wid == 1) {
        float ts = (lane < NWARPS) ? sumw[lane] : 0.0f;
        float tq = (lane < NWARPS) ? sqw[lane]  : 0.0f;
        #pragma unroll
        for (int off = 4; off > 0; off >>= 1) {
            ts += __shfl_xor_sync(FULL, ts, off);
            tq += __shfl_xor_sync(FULL, tq, off);
        }
        if (lane == 0) {
            s0_sh = (tq - ts * ts * (1.0f / (float)T_LEN))
                    * (1.0f / (float)(T_LEN - 1));
        }
    }
    __syncthreads();
    const float s0 = s0_sh;

    // ---- chain segment base states: S_{j+1} = Afull_j * S_j + Bfull_j ----
    float S[NSEG];
    S[0] = s0;
    #pragma unroll
    for (int j = 0; j < NSEG - 1; j++)
        S[j + 1] = fmaf(AwS[j][NWARPS - 1], S[j], BwS[j][NWARPS - 1]);

    // ---- thread-exclusive prefix within each segment ----
    float a_exc[NSEG], b_exc[NSEG];
    #pragma unroll
    for (int j = 0; j < NSEG; j++) {
        a_exc[j] = __shfl_up_sync(FULL, A[j], 1);
        b_exc[j] = __shfl_up_sync(FULL, B[j], 1);
        if (lane == 0) { a_exc[j] = 1.0f; b_exc[j] = 0.0f; }
    }

    // ---- replay all 4 segments (independent chains -> MUFU/FMA ILP) ----
    #pragma unroll
    for (int j = 0; j < NSEG; j++) {
        float a_wp = 1.0f, b_wp = 0.0f;
        if (wid > 0) { a_wp = AwS[j][wid - 1]; b_wp = BwS[j][wid - 1]; }
        // compose warp-prefix (earlier) then thread-exclusive (later), apply to S[j]
        float s = fmaf(a_exc[j] * a_wp, S[j], fmaf(a_exc[j], b_wp, b_exc[j]));

        float4 o;
        o.x = s * rsqrtf(s);
        s = fmaf(beta, s, fmaf(alpha, v[j].x * v[j].x, omega));
        o.y = s * rsqrtf(s);
        s = fmaf(beta, s, fmaf(alpha, v[j].y * v[j].y, omega));
        o.z = s * rsqrtf(s);
        s = fmaf(beta, s, fmaf(alpha, v[j].z * v[j].z, omega));
        o.w = s * rsqrtf(s);

        out4[row4 + j * NTHREADS + tid] = o;
    }
}

extern "C" void kernel_launch(void* const* d_in, const int* in_sizes, int n_in,
                              void* d_out, int out_size)
{
    const float4* x4       = (const float4*)d_in[0];
    const float* omega_log = (const float*)d_in[1];
    const float* alpha_log = (const float*)d_in[2];
    const float* beta_log  = (const float*)d_in[3];
    float4* out4 = (float4*)d_out;

    const int B = in_sizes[0] / T_LEN;   // 4096 rows
    garch_kernel<<<B, NTHREADS>>>(x4, omega_log, alpha_log, beta_log, out4);
}